// round 1
// baseline (speedup 1.0000x reference)
#include <cuda_runtime.h>
#include <math.h>

#define NPTS 500
#define NNP  8
#define NSEL 4000   // NPTS * NNP

// ---------------- device scratch (no allocations allowed) ----------------
__device__ int   g_inds[NSEL];
__device__ int   g_inds_tc[NSEL];
__device__ float g_expw[NSEL];
__device__ float g_expw_tc[NSEL];
__device__ float g_invS8[2];
__device__ float g_cf [128 * NPTS];   // cloud_feat
__device__ float g_sf [128 * NPTS];
__device__ float g_sfp[128 * NPTS];
__device__ float g_wt [118976];       // all transposed weights (k-major)

// offsets into g_wt (floats)
#define OFF_PCONV1T  0        // [3][64]
#define OFF_PCONV2T  192      // [64][128]
#define OFF_CONV1T   8384     // [32][64]
#define OFF_CONV2T   10432    // [64][128]
#define OFF_PSCONV1T 18624    // [128][256]
#define OFF_PSCONV2T 51392    // [256][128]
#define OFF_FC1T     84160    // [256][64]
#define OFF_FC2T     100544   // [160][64]
#define OFF_FCT      110784   // [128][64]

// ---------------- transpose all weights to k-major -----------------------
__device__ __forceinline__ void tp_one(const float* src, int M, int K, int off,
                                       int t, int nt) {
    for (int i = t; i < M * K; i += nt) {
        int m = i / K, k = i - m * K;
        g_wt[off + k * M + m] = src[i];
    }
}

__global__ void k_transpose(const float* wc1, const float* wc2,
                            const float* wps1, const float* wps2,
                            const float* wp1, const float* wp2,
                            const float* wf1, const float* wf2,
                            const float* wf) {
    int t  = blockIdx.x * blockDim.x + threadIdx.x;
    int nt = gridDim.x * blockDim.x;
    tp_one(wp1,  64,  3,   OFF_PCONV1T,  t, nt);
    tp_one(wp2,  128, 64,  OFF_PCONV2T,  t, nt);
    tp_one(wc1,  64,  32,  OFF_CONV1T,   t, nt);
    tp_one(wc2,  128, 64,  OFF_CONV2T,   t, nt);
    tp_one(wps1, 256, 128, OFF_PSCONV1T, t, nt);
    tp_one(wps2, 128, 256, OFF_PSCONV2T, t, nt);
    tp_one(wf1,  64,  256, OFF_FC1T,     t, nt);
    tp_one(wf2,  64,  160, OFF_FC2T,     t, nt);
    tp_one(wf,   64,  128, OFF_FCT,      t, nt);
}

// ---------------- kNN: one warp per query point ---------------------------
// warp id < 500  : query = cloud[w],      ref = cloud_tar -> g_inds / g_expw
// warp id >= 500 : query = cloud_tar[w'], ref = cloud     -> g_inds_tc / g_expw_tc
__global__ __launch_bounds__(128)
void k_knn(const float* __restrict__ cloud, const float* __restrict__ cloud_tar) {
    __shared__ float sc[NPTS * 3];
    __shared__ float st[NPTS * 3];
    const int tid = threadIdx.x;
    for (int i = tid; i < NPTS * 3; i += 128) {
        sc[i] = cloud[i];
        st[i] = cloud_tar[i];
    }
    __syncthreads();

    const int warp = blockIdx.x * 4 + (tid >> 5);
    const int lane = tid & 31;
    if (warp >= 2 * NPTS) return;

    const bool tc = (warp >= NPTS);
    const int  q  = tc ? warp - NPTS : warp;
    const float* qs = tc ? st : sc;
    const float* rs = tc ? sc : st;

    const float qx = qs[q * 3 + 0], qy = qs[q * 3 + 1], qz = qs[q * 3 + 2];
    const float qq = qx * qx + qy * qy + qz * qz;
    const float INF = __int_as_float(0x7f800000);

    float vals[16];
#pragma unroll
    for (int k = 0; k < 16; k++) {
        int r = lane + 32 * k;
        if (r < NPTS) {
            float rx = rs[r * 3 + 0], ry = rs[r * 3 + 1], rz = rs[r * 3 + 2];
            float rr = rx * rx + ry * ry + rz * rz;
            float dt = qx * rx + qy * ry + qz * rz;
            vals[k] = fmaxf(qq - 2.f * dt + rr, 0.f);   // expansion formula (matches ref selection)
        } else {
            vals[k] = INF;
        }
    }

    int*   oinds = tc ? g_inds_tc : g_inds;
    float* oexp  = tc ? g_expw_tc : g_expw;

    for (int r8 = 0; r8 < NNP; r8++) {
        float bv = vals[0];
        int   bk = 0;
#pragma unroll
        for (int k = 1; k < 16; k++)
            if (vals[k] < bv) { bv = vals[k]; bk = k; }
        unsigned long long key =
            (((unsigned long long)__float_as_uint(bv)) << 32) |
            (unsigned)(lane + 32 * bk);
#pragma unroll
        for (int s = 16; s; s >>= 1) {
            unsigned long long o = __shfl_xor_sync(0xffffffffu, key, s);
            if (o < key) key = o;
        }
        const int gi = (int)(key & 0xffffffffu);
#pragma unroll
        for (int k = 0; k < 16; k++)
            if (lane + 32 * k == gi) vals[k] = INF;
        if (lane == 0) {
            float dx = qx - rs[gi * 3 + 0];
            float dy = qy - rs[gi * 3 + 1];
            float dz = qz - rs[gi * 3 + 2];
            float nrm = sqrtf(dx * dx + dy * dy + dz * dz);  // matches reference norm
            oinds[q * NNP + r8] = gi;
            oexp [q * NNP + r8] = expf(-nrm);
        }
    }
}

// ---------------- deterministic softmax denominators ----------------------
__global__ __launch_bounds__(256)
void k_sums() {
    __shared__ float r0[256], r1[256];
    int t = threadIdx.x;
    float s0 = 0.f, s1 = 0.f;
    for (int i = t; i < NSEL; i += 256) {
        s0 += g_expw[i];
        s1 += g_expw_tc[i];
    }
    r0[t] = s0; r1[t] = s1;
    __syncthreads();
    for (int s = 128; s > 0; s >>= 1) {
        if (t < s) { r0[t] += r0[t + s]; r1[t] += r1[t + s]; }
        __syncthreads();
    }
    if (t == 0) {
        g_invS8[0] = 1.f / (8.f * r0[0]);
        g_invS8[1] = 1.f / (8.f * r1[0]);
    }
}

// ---------------- 16-wide FMA helper --------------------------------------
__device__ __forceinline__ void fma16(float* a, float w,
                                      float4 x0, float4 x1, float4 x2, float4 x3) {
    a[0]  += w * x0.x; a[1]  += w * x0.y; a[2]  += w * x0.z; a[3]  += w * x0.w;
    a[4]  += w * x1.x; a[5]  += w * x1.y; a[6]  += w * x1.z; a[7]  += w * x1.w;
    a[8]  += w * x2.x; a[9]  += w * x2.y; a[10] += w * x2.z; a[11] += w * x2.w;
    a[12] += w * x3.x; a[13] += w * x3.y; a[14] += w * x3.z; a[15] += w * x3.w;
}

// ---------------- fused 2-layer MLP on (optionally gathered) columns ------
// Y = W2 @ lrelu(W1 @ X[:, g] + b1) + b2 ; optional per-column softmax weight
// + mean-over-8 reduction. 16 columns per block, 128 threads.
// GSEL: 0 = no gather (write g_cf), 1 = inds/expw -> g_sf, 2 = inds_tc -> g_sfp
template <int KIN, int KHID, int KOUT, int RS, int CS, int GSEL,
          int W1OFF, int W2OFF>
__global__ __launch_bounds__(128)
void k_mlp(const float* __restrict__ Xp,
           const float* __restrict__ b1, const float* __restrict__ b2,
           int ncols) {
    static_assert(KOUT == 128, "KOUT must equal blockDim");
    __shared__ __align__(16) float Xs[KIN][16];
    __shared__ __align__(16) float Hs[KHID][16];
    __shared__ float cw[16];

    const int tid  = threadIdx.x;
    const int col0 = blockIdx.x * 16;

    const float* X = (GSEL == 2) ? g_cf : Xp;
    const int*   gidx = (GSEL == 1) ? g_inds : g_inds_tc;
    const float* ew   = (GSEL == 1) ? g_expw : g_expw_tc;

    for (int i = tid; i < KIN * 16; i += 128) {
        int c = i & 15, k = i >> 4;
        int col = col0 + c;
        float v = 0.f;
        if (col < ncols) {
            int g = (GSEL == 0) ? col : gidx[col];
            v = X[k * RS + g * CS];
        }
        Xs[k][c] = v;
    }
    if (GSEL != 0 && tid < 16)
        cw[tid] = ew[col0 + tid] * g_invS8[GSEL - 1];
    __syncthreads();

    // ---- phase 1: H = lrelu(W1 @ X + b1) ----
    constexpr int R1 = (KHID + 127) / 128;
    float acc[R1][16];
#pragma unroll
    for (int rr = 0; rr < R1; rr++)
#pragma unroll
        for (int c = 0; c < 16; c++) acc[rr][c] = 0.f;

#pragma unroll 2
    for (int k = 0; k < KIN; k++) {
        const float4* xp = (const float4*)Xs[k];
        float4 x0 = xp[0], x1 = xp[1], x2 = xp[2], x3 = xp[3];
#pragma unroll
        for (int rr = 0; rr < R1; rr++) {
            int row = tid + rr * 128;
            float w = 0.f;
            if (KHID == R1 * 128 || row < KHID)
                w = g_wt[W1OFF + k * KHID + row];
            fma16(acc[rr], w, x0, x1, x2, x3);
        }
    }
#pragma unroll
    for (int rr = 0; rr < R1; rr++) {
        int row = tid + rr * 128;
        if (row < KHID) {
            float b = b1[row];
#pragma unroll
            for (int c = 0; c < 16; c++) {
                float v = acc[rr][c] + b;
                Hs[row][c] = (v >= 0.f) ? v : 0.01f * v;
            }
        }
    }
    __syncthreads();

    // ---- phase 2: Y = W2 @ H (+ b2) ----
    float a2[16];
#pragma unroll
    for (int c = 0; c < 16; c++) a2[c] = 0.f;
#pragma unroll 2
    for (int k = 0; k < KHID; k++) {
        const float4* hp = (const float4*)Hs[k];
        float4 x0 = hp[0], x1 = hp[1], x2 = hp[2], x3 = hp[3];
        float w = g_wt[W2OFF + k * KOUT + tid];
        fma16(a2, w, x0, x1, x2, x3);
    }
    float b = b2[tid];

    if (GSEL == 0) {
#pragma unroll
        for (int c = 0; c < 16; c++) {
            int col = col0 + c;
            if (col < ncols) g_cf[tid * NPTS + col] = a2[c] + b;
        }
    } else {
        float* out = (GSEL == 1) ? g_sf : g_sfp;
#pragma unroll
        for (int p = 0; p < 2; p++) {
            float s = 0.f;
#pragma unroll
            for (int j = 0; j < 8; j++) {
                int c = p * 8 + j;
                s += (a2[c] + b) * cw[c];
            }
            out[tid * NPTS + (col0 >> 3) + p] = s;
        }
    }
}

// ---------------- final FC stack ------------------------------------------
// f1 = Wfc1 @ [sf; cf] + b ; f2 = Wfc2 @ [sfp; imf] + b
// out = Wfc @ lrelu([f2; f1]) + bfc
__global__ __launch_bounds__(128)
void k_final(const float* __restrict__ imf,
             const float* __restrict__ bfc1, const float* __restrict__ bfc2,
             const float* __restrict__ bfc, float* __restrict__ out) {
    __shared__ __align__(16) float X1[256][16];
    __shared__ __align__(16) float X2[160][16];
    __shared__ __align__(16) float G[128][16];

    const int tid  = threadIdx.x;
    const int col0 = blockIdx.x * 16;

    for (int i = tid; i < 256 * 16; i += 128) {
        int c = i & 15, k = i >> 4;
        int col = col0 + c;
        float v = 0.f;
        if (col < NPTS)
            v = (k < 128) ? g_sf[k * NPTS + col] : g_cf[(k - 128) * NPTS + col];
        X1[k][c] = v;
    }
    for (int i = tid; i < 160 * 16; i += 128) {
        int c = i & 15, k = i >> 4;
        int col = col0 + c;
        float v = 0.f;
        if (col < NPTS)
            v = (k < 128) ? g_sfp[k * NPTS + col] : imf[(k - 128) * NPTS + col];
        X2[k][c] = v;
    }
    __syncthreads();

    float a[16];
#pragma unroll
    for (int c = 0; c < 16; c++) a[c] = 0.f;
    float b;
    if (tid < 64) {           // f2 rows (concat order [f2; f1])
#pragma unroll 2
        for (int k = 0; k < 160; k++) {
            const float4* xp = (const float4*)X2[k];
            float4 x0 = xp[0], x1 = xp[1], x2 = xp[2], x3 = xp[3];
            float w = g_wt[OFF_FC2T + k * 64 + tid];
            fma16(a, w, x0, x1, x2, x3);
        }
        b = bfc2[tid];
    } else {                  // f1 rows
#pragma unroll 2
        for (int k = 0; k < 256; k++) {
            const float4* xp = (const float4*)X1[k];
            float4 x0 = xp[0], x1 = xp[1], x2 = xp[2], x3 = xp[3];
            float w = g_wt[OFF_FC1T + k * 64 + (tid - 64)];
            fma16(a, w, x0, x1, x2, x3);
        }
        b = bfc1[tid - 64];
    }
#pragma unroll
    for (int c = 0; c < 16; c++) {
        float v = a[c] + b;
        G[tid][c] = (v >= 0.f) ? v : 0.01f * v;
    }
    __syncthreads();

    if (tid < 64) {
        float o[16];
#pragma unroll
        for (int c = 0; c < 16; c++) o[c] = 0.f;
#pragma unroll 2
        for (int k = 0; k < 128; k++) {
            const float4* gp = (const float4*)G[k];
            float4 x0 = gp[0], x1 = gp[1], x2 = gp[2], x3 = gp[3];
            float w = g_wt[OFF_FCT + k * 64 + tid];
            fma16(o, w, x0, x1, x2, x3);
        }
        float bb = bfc[tid];
#pragma unroll
        for (int c = 0; c < 16; c++) {
            int col = col0 + c;
            if (col < NPTS) out[tid * NPTS + col] = o[c] + bb;
        }
    }
}

// ---------------- launch ---------------------------------------------------
extern "C" void kernel_launch(void* const* d_in, const int* in_sizes, int n_in,
                              void* d_out, int out_size) {
    const float* imf       = (const float*)d_in[0];
    const float* cloud     = (const float*)d_in[1];
    const float* cloud_tar = (const float*)d_in[2];
    const float* w_conv1   = (const float*)d_in[3];
    const float* b_conv1   = (const float*)d_in[4];
    const float* w_conv2   = (const float*)d_in[5];
    const float* b_conv2   = (const float*)d_in[6];
    const float* w_psconv1 = (const float*)d_in[7];
    const float* b_psconv1 = (const float*)d_in[8];
    const float* w_psconv2 = (const float*)d_in[9];
    const float* b_psconv2 = (const float*)d_in[10];
    const float* w_pconv1  = (const float*)d_in[11];
    const float* b_pconv1  = (const float*)d_in[12];
    const float* w_pconv2  = (const float*)d_in[13];
    const float* b_pconv2  = (const float*)d_in[14];
    const float* w_fc1     = (const float*)d_in[15];
    const float* b_fc1     = (const float*)d_in[16];
    const float* w_fc2     = (const float*)d_in[17];
    const float* b_fc2     = (const float*)d_in[18];
    const float* w_fc      = (const float*)d_in[19];
    const float* b_fc      = (const float*)d_in[20];
    float* out = (float*)d_out;

    k_transpose<<<64, 256>>>(w_conv1, w_conv2, w_psconv1, w_psconv2,
                             w_pconv1, w_pconv2, w_fc1, w_fc2, w_fc);
    k_knn<<<250, 128>>>(cloud, cloud_tar);
    k_sums<<<1, 256>>>();

    // cloud_feat: 3 -> 64 -> 128 on cloud^T (cloud stored [500][3])
    k_mlp<3, 64, 128, 1, 3, 0, OFF_PCONV1T, OFF_PCONV2T>
        <<<32, 128>>>(cloud, b_pconv1, b_pconv2, NPTS);

    // sf: gather imf by inds, 32 -> 64 -> 128, softmax-weighted mean8
    k_mlp<32, 64, 128, NPTS, 1, 1, OFF_CONV1T, OFF_CONV2T>
        <<<250, 128>>>(imf, b_conv1, b_conv2, NSEL);

    // sfp: gather cloud_feat by inds_tc, 128 -> 256 -> 128, weighted mean8
    k_mlp<128, 256, 128, NPTS, 1, 2, OFF_PSCONV1T, OFF_PSCONV2T>
        <<<250, 128>>>(nullptr, b_psconv1, b_psconv2, NSEL);

    k_final<<<32, 128>>>(imf, b_fc1, b_fc2, b_fc, out);
}

// round 11
// speedup vs baseline: 1.8655x; 1.8655x over previous
#include <cuda_runtime.h>
#include <math.h>

#define NPTS 500
#define NNP  8
#define NSEL 4000   // NPTS * NNP

// ---------------- device scratch (no allocations allowed) ----------------
__device__ int   g_inds[NSEL];
__device__ int   g_inds_tc[NSEL];
__device__ float g_expw[NSEL];
__device__ float g_expw_tc[NSEL];
__device__ float g_cf [128 * NPTS];   // cloud_feat
__device__ float g_sf [128 * NPTS];
__device__ float g_sfp[128 * NPTS];

typedef unsigned long long u64;

// ---------------- packed f32x2 helpers (FFMA2) ----------------------------
__device__ __forceinline__ u64 packww(float w) {
    unsigned u = __float_as_uint(w);
    u64 r;
    asm("mov.b64 %0, {%1, %1};" : "=l"(r) : "r"(u));
    return r;
}
__device__ __forceinline__ void ffma2(u64& a, u64 w, u64 x) {
    asm("fma.rn.f32x2 %0, %1, %2, %0;" : "+l"(a) : "l"(w), "l"(x));
}
__device__ __forceinline__ float2 upk(u64 a) {
    unsigned lo, hi;
    asm("mov.b64 {%0, %1}, %2;" : "=r"(lo), "=r"(hi) : "l"(a));
    return make_float2(__uint_as_float(lo), __uint_as_float(hi));
}

// ---------------- stage weights [M][K] -> smem k-major, padded ------------
// Ws[k*(M+1) + m] = src[m*K + k].  Thread-per-row => conflict-free STS,
// per-thread K/4 independent LDG.128 (latency well hidden).
template <int M, int K>
__device__ __forceinline__ void stage_w(float* Ws, const float* __restrict__ src,
                                        int tid) {
    constexpr int Mp = M + 1;
    if (K % 4 == 0) {
        for (int m = tid; m < M; m += 128) {
            const float4* row = (const float4*)(src + m * K);
#pragma unroll 4
            for (int k4 = 0; k4 < K / 4; k4++) {
                float4 v = row[k4];
                Ws[(4 * k4 + 0) * Mp + m] = v.x;
                Ws[(4 * k4 + 1) * Mp + m] = v.y;
                Ws[(4 * k4 + 2) * Mp + m] = v.z;
                Ws[(4 * k4 + 3) * Mp + m] = v.w;
            }
        }
    } else {
        for (int i = tid; i < M * K; i += 128) {
            int m = i / K, k = i - m * K;
            Ws[k * Mp + m] = src[i];
        }
    }
}

// ---------------- kNN: one warp per query point ---------------------------
__global__ __launch_bounds__(128)
void k_knn(const float* __restrict__ cloud, const float* __restrict__ cloud_tar) {
    __shared__ float sc[NPTS * 3];
    __shared__ float st[NPTS * 3];
    const int tid = threadIdx.x;
    for (int i = tid; i < NPTS * 3; i += 128) {
        sc[i] = cloud[i];
        st[i] = cloud_tar[i];
    }
    __syncthreads();

    const int warp = blockIdx.x * 4 + (tid >> 5);
    const int lane = tid & 31;
    if (warp >= 2 * NPTS) return;

    const bool tc = (warp >= NPTS);
    const int  q  = tc ? warp - NPTS : warp;
    const float* qs = tc ? st : sc;
    const float* rs = tc ? sc : st;

    const float qx = qs[q * 3 + 0], qy = qs[q * 3 + 1], qz = qs[q * 3 + 2];
    const float qq = qx * qx + qy * qy + qz * qz;
    const float INF = __int_as_float(0x7f800000);

    float vals[16];
#pragma unroll
    for (int k = 0; k < 16; k++) {
        int r = lane + 32 * k;
        if (r < NPTS) {
            float rx = rs[r * 3 + 0], ry = rs[r * 3 + 1], rz = rs[r * 3 + 2];
            float rr = rx * rx + ry * ry + rz * rz;
            float dt = qx * rx + qy * ry + qz * rz;
            vals[k] = fmaxf(qq - 2.f * dt + rr, 0.f);
        } else {
            vals[k] = INF;
        }
    }

    int*   oinds = tc ? g_inds_tc : g_inds;
    float* oexp  = tc ? g_expw_tc : g_expw;

    for (int r8 = 0; r8 < NNP; r8++) {
        float bv = vals[0];
        int   bk = 0;
#pragma unroll
        for (int k = 1; k < 16; k++)
            if (vals[k] < bv) { bv = vals[k]; bk = k; }
        u64 key = (((u64)__float_as_uint(bv)) << 32) | (unsigned)(lane + 32 * bk);
#pragma unroll
        for (int s = 16; s; s >>= 1) {
            u64 o = __shfl_xor_sync(0xffffffffu, key, s);
            if (o < key) key = o;
        }
        const int gi = (int)(key & 0xffffffffu);
#pragma unroll
        for (int k = 0; k < 16; k++)
            if (lane + 32 * k == gi) vals[k] = INF;
        if (lane == 0) {
            float dx = qx - rs[gi * 3 + 0];
            float dy = qy - rs[gi * 3 + 1];
            float dz = qz - rs[gi * 3 + 2];
            float nrm = sqrtf(dx * dx + dy * dy + dz * dz);
            oinds[q * NNP + r8] = gi;
            oexp [q * NNP + r8] = expf(-nrm);
        }
    }
}

// ---------------- fused 2-layer MLP, smem-staged weights ------------------
__host__ __device__ constexpr int ws_floats(int KIN, int KHID) {
    int a = KIN * (KHID + 1);
    int b = KHID * 129;
    return a > b ? a : b;
}
__host__ __device__ constexpr int mlp_smem_floats(int KIN, int KHID, int COLS) {
    return ws_floats(KIN, KHID) + KIN * COLS + KHID * (COLS + 2) + COLS + 128;
}

// GSEL: 0 = pconv path (X = cloud [500][3], write g_cf)
//       1 = conv path  (gather imf by g_inds, weighted mean -> g_sf)
//       2 = psconv path(gather g_cf by g_inds_tc, weighted mean -> g_sfp)
template <int KIN, int KHID, int COLS, int GSEL>
__global__ __launch_bounds__(128, 1)
void k_mlp(const float* __restrict__ Xg,
           const float* __restrict__ w1, const float* __restrict__ b1,
           const float* __restrict__ w2, const float* __restrict__ b2) {
    constexpr int HP = COLS + 2;
    constexpr int WS = ws_floats(KIN, KHID);
    constexpr int R1 = (KHID + 127) / 128;
    constexpr int J  = COLS / 2;
    extern __shared__ float sm[];
    float* Ws  = sm;
    float* Xs  = sm + WS;
    float* Hs  = Xs + KIN * COLS;
    float* cw  = Hs + KHID * HP;
    float* red = cw + COLS;

    const int tid  = threadIdx.x;
    const int col0 = blockIdx.x * COLS;

    const int*   gidx = (GSEL == 1) ? g_inds : g_inds_tc;
    const float* ew   = (GSEL == 1) ? g_expw : g_expw_tc;

    if (GSEL != 0) {              // block-local deterministic softmax denom
        float s = 0.f;
        for (int i = tid; i < NSEL; i += 128) s += ew[i];
        red[tid] = s;
    }

    stage_w<KHID, KIN>(Ws, w1, tid);

    const float* X = (GSEL == 2) ? (const float*)g_cf : Xg;
    for (int i = tid; i < KIN * COLS; i += 128) {
        int c = i % COLS, k = i / COLS;
        int col = col0 + c;
        float v = 0.f;
        if (GSEL == 0) {
            if (col < NPTS) v = X[col * 3 + k];        // cloud is [500][3]
        } else {
            v = X[k * NPTS + gidx[col]];
        }
        Xs[k * COLS + c] = v;
    }
    __syncthreads();

    if (GSEL != 0 && tid < 32) {
        float s = red[tid] + red[tid + 32] + red[tid + 64] + red[tid + 96];
#pragma unroll
        for (int o = 16; o; o >>= 1) s += __shfl_xor_sync(0xffffffffu, s, o);
        if (tid == 0) red[0] = 1.f / (8.f * s);
    }

    // ---- phase 1: H = lrelu(W1 @ X + b1) ----
    u64 acc[R1][J];
#pragma unroll
    for (int rr = 0; rr < R1; rr++)
#pragma unroll
        for (int j = 0; j < J; j++) acc[rr][j] = 0ull;

    for (int k = 0; k < KIN; k++) {
        u64 xv[J];
        const u64* xp = (const u64*)(Xs + k * COLS);
#pragma unroll
        for (int j = 0; j < J; j++) xv[j] = xp[j];
#pragma unroll
        for (int rr = 0; rr < R1; rr++) {
            int row = tid + rr * 128;
            if ((KHID % 128 == 0) || row < KHID) {
                u64 wp = packww(Ws[k * (KHID + 1) + row]);
#pragma unroll
                for (int j = 0; j < J; j++) ffma2(acc[rr][j], wp, xv[j]);
            }
        }
    }
#pragma unroll
    for (int rr = 0; rr < R1; rr++) {
        int row = tid + rr * 128;
        if (row < KHID) {
            float b = b1[row];
#pragma unroll
            for (int j = 0; j < J; j++) {
                float2 v = upk(acc[rr][j]);
                v.x += b; v.y += b;
                v.x = (v.x >= 0.f) ? v.x : 0.01f * v.x;
                v.y = (v.y >= 0.f) ? v.y : 0.01f * v.y;
                *(float2*)(Hs + row * HP + 2 * j) = v;
            }
        }
    }
    __syncthreads();

    stage_w<128, KHID>(Ws, w2, tid);   // overwrite Ws with W2 (safe post-sync)
    if (GSEL != 0 && tid < COLS)
        cw[tid] = ew[col0 + tid] * red[0];
    __syncthreads();

    // ---- phase 2: Y = W2 @ H + b2 ----
    u64 a2[J];
#pragma unroll
    for (int j = 0; j < J; j++) a2[j] = 0ull;
    for (int k = 0; k < KHID; k++) {
        u64 xv[J];
        const u64* hp = (const u64*)(Hs + k * HP);
#pragma unroll
        for (int j = 0; j < J; j++) xv[j] = hp[j];
        u64 wp = packww(Ws[k * 129 + tid]);
#pragma unroll
        for (int j = 0; j < J; j++) ffma2(a2[j], wp, xv[j]);
    }
    float bb = b2[tid];

    if (GSEL == 0) {
#pragma unroll
        for (int j = 0; j < J; j++) {
            float2 v = upk(a2[j]);
            int c = 2 * j;
            if (col0 + c < NPTS)     g_cf[tid * NPTS + col0 + c]     = v.x + bb;
            if (col0 + c + 1 < NPTS) g_cf[tid * NPTS + col0 + c + 1] = v.y + bb;
        }
    } else {
        float* outb = (GSEL == 1) ? g_sf : g_sfp;
#pragma unroll
        for (int p = 0; p < COLS / 8; p++) {
            float s = 0.f;
#pragma unroll
            for (int j = 0; j < 4; j++) {
                float2 v = upk(a2[p * 4 + j]);
                s += (v.x + bb) * cw[p * 8 + 2 * j];
                s += (v.y + bb) * cw[p * 8 + 2 * j + 1];
            }
            outb[tid * NPTS + (col0 >> 3) + p] = s;
        }
    }
}

// ---------------- final FC stack ------------------------------------------
// f1 = Wfc1 @ [sf; cf], f2 = Wfc2 @ [sfp; imf], out = Wfc @ lrelu([f2; f1])
#define FW2 10400   // 160*65
#define FW1 16640   // 256*65
#define FWF 8320    // 128*65
#define FINAL_SMEM_FLOATS (FW2 + FW1 + FWF + 256*16 + 160*16 + 128*18)

__global__ __launch_bounds__(128, 1)
void k_final(const float* __restrict__ imf,
             const float* __restrict__ wf1, const float* __restrict__ bf1,
             const float* __restrict__ wf2, const float* __restrict__ bf2,
             const float* __restrict__ wf,  const float* __restrict__ bf,
             float* __restrict__ out) {
    extern __shared__ float sm[];
    float* W2s = sm;              // [160][65]
    float* W1s = W2s + FW2;       // [256][65]
    float* WFs = W1s + FW1;       // [128][65]
    float* X1  = WFs + FWF;       // [256][16]
    float* X2  = X1 + 256 * 16;   // [160][16]
    float* G   = X2 + 160 * 16;   // [128][18]

    const int tid  = threadIdx.x;
    const int col0 = blockIdx.x * 16;

    stage_w<64, 160>(W2s, wf2, tid);
    stage_w<64, 256>(W1s, wf1, tid);
    stage_w<64, 128>(WFs, wf,  tid);

    for (int i = tid; i < 256 * 16; i += 128) {
        int c = i & 15, k = i >> 4;
        int col = col0 + c;
        float v = 0.f;
        if (col < NPTS)
            v = (k < 128) ? g_sf[k * NPTS + col] : g_cf[(k - 128) * NPTS + col];
        X1[k * 16 + c] = v;
    }
    for (int i = tid; i < 160 * 16; i += 128) {
        int c = i & 15, k = i >> 4;
        int col = col0 + c;
        float v = 0.f;
        if (col < NPTS)
            v = (k < 128) ? g_sfp[k * NPTS + col] : imf[(k - 128) * NPTS + col];
        X2[k * 16 + c] = v;
    }
    __syncthreads();

    u64 a[8];
#pragma unroll
    for (int j = 0; j < 8; j++) a[j] = 0ull;
    float b;
    if (tid < 64) {               // f2 rows (concat order [f2; f1])
        for (int k = 0; k < 160; k++) {
            const u64* xp = (const u64*)(X2 + k * 16);
            u64 wp = packww(W2s[k * 65 + tid]);
#pragma unroll
            for (int j = 0; j < 8; j++) ffma2(a[j], wp, xp[j]);
        }
        b = bf2[tid];
    } else {                      // f1 rows
        for (int k = 0; k < 256; k++) {
            const u64* xp = (const u64*)(X1 + k * 16);
            u64 wp = packww(W1s[k * 65 + (tid - 64)]);
#pragma unroll
            for (int j = 0; j < 8; j++) ffma2(a[j], wp, xp[j]);
        }
        b = bf1[tid - 64];
    }
#pragma unroll
    for (int j = 0; j < 8; j++) {
        float2 v = upk(a[j]);
        v.x += b; v.y += b;
        v.x = (v.x >= 0.f) ? v.x : 0.01f * v.x;
        v.y = (v.y >= 0.f) ? v.y : 0.01f * v.y;
        *(float2*)(G + tid * 18 + 2 * j) = v;
    }
    __syncthreads();

    if (tid < 64) {
        u64 o[8];
#pragma unroll
        for (int j = 0; j < 8; j++) o[j] = 0ull;
        for (int k = 0; k < 128; k++) {
            const u64* gp = (const u64*)(G + k * 18);
            u64 wp = packww(WFs[k * 65 + tid]);
#pragma unroll
            for (int j = 0; j < 8; j++) ffma2(o[j], wp, gp[j]);
        }
        float bb = bf[tid];
#pragma unroll
        for (int j = 0; j < 8; j++) {
            float2 v = upk(o[j]);
            int c = 2 * j;
            if (col0 + c < NPTS)     out[tid * NPTS + col0 + c]     = v.x + bb;
            if (col0 + c + 1 < NPTS) out[tid * NPTS + col0 + c + 1] = v.y + bb;
        }
    }
}

// ---------------- launch ---------------------------------------------------
extern "C" void kernel_launch(void* const* d_in, const int* in_sizes, int n_in,
                              void* d_out, int out_size) {
    const float* imf       = (const float*)d_in[0];
    const float* cloud     = (const float*)d_in[1];
    const float* cloud_tar = (const float*)d_in[2];
    const float* w_conv1   = (const float*)d_in[3];
    const float* b_conv1   = (const float*)d_in[4];
    const float* w_conv2   = (const float*)d_in[5];
    const float* b_conv2   = (const float*)d_in[6];
    const float* w_psconv1 = (const float*)d_in[7];
    const float* b_psconv1 = (const float*)d_in[8];
    const float* w_psconv2 = (const float*)d_in[9];
    const float* b_psconv2 = (const float*)d_in[10];
    const float* w_pconv1  = (const float*)d_in[11];
    const float* b_pconv1  = (const float*)d_in[12];
    const float* w_pconv2  = (const float*)d_in[13];
    const float* b_pconv2  = (const float*)d_in[14];
    const float* w_fc1     = (const float*)d_in[15];
    const float* b_fc1     = (const float*)d_in[16];
    const float* w_fc2     = (const float*)d_in[17];
    const float* b_fc2     = (const float*)d_in[18];
    const float* w_fc      = (const float*)d_in[19];
    const float* b_fc      = (const float*)d_in[20];
    float* out = (float*)d_out;

    const int S0 = mlp_smem_floats(3, 64, 32) * 4;
    const int S1 = mlp_smem_floats(32, 64, 32) * 4;
    const int S2 = mlp_smem_floats(128, 256, 32) * 4;
    const int SF = FINAL_SMEM_FLOATS * 4;

    cudaFuncSetAttribute(k_mlp<3, 64, 32, 0>,
                         cudaFuncAttributeMaxDynamicSharedMemorySize, S0);
    cudaFuncSetAttribute(k_mlp<32, 64, 32, 1>,
                         cudaFuncAttributeMaxDynamicSharedMemorySize, S1);
    cudaFuncSetAttribute(k_mlp<128, 256, 32, 2>,
                         cudaFuncAttributeMaxDynamicSharedMemorySize, S2);
    cudaFuncSetAttribute(k_final,
                         cudaFuncAttributeMaxDynamicSharedMemorySize, SF);

    k_knn<<<250, 128>>>(cloud, cloud_tar);

    // cloud_feat: 3 -> 64 -> 128 over 500 points
    k_mlp<3, 64, 32, 0><<<(NPTS + 31) / 32, 128, S0>>>(
        cloud, w_pconv1, b_pconv1, w_pconv2, b_pconv2);

    // sf: gather imf by inds, 32 -> 64 -> 128, softmax-weighted mean8
    k_mlp<32, 64, 32, 1><<<NSEL / 32, 128, S1>>>(
        imf, w_conv1, b_conv1, w_conv2, b_conv2);

    // sfp: gather cloud_feat by inds_tc, 128 -> 256 -> 128, weighted mean8
    k_mlp<128, 256, 32, 2><<<NSEL / 32, 128, S2>>>(
        nullptr, w_psconv1, b_psconv1, w_psconv2, b_psconv2);

    k_final<<<(NPTS + 15) / 16, 128, SF>>>(
        imf, w_fc1, b_fc1, w_fc2, b_fc2, w_fc, b_fc, out);
}

// round 15
// speedup vs baseline: 1.9492x; 1.0448x over previous
#include <cuda_runtime.h>
#include <math.h>

#define NPTS 500
#define NNP  8
#define NSEL 4000   // NPTS * NNP

// ---------------- device scratch (no allocations allowed) ----------------
__device__ int   g_inds[NSEL];
__device__ int   g_inds_tc[NSEL];
__device__ float g_expw[NSEL];
__device__ float g_expw_tc[NSEL];
__device__ float g_cf [128 * NPTS];   // cloud_feat
__device__ float g_sf [128 * NPTS];
__device__ float g_sfp[128 * NPTS];

typedef unsigned long long u64;

// ---------------- packed f32x2 helpers (FFMA2) ----------------------------
__device__ __forceinline__ u64 packww(float w) {
    unsigned u = __float_as_uint(w);
    u64 r;
    asm("mov.b64 %0, {%1, %1};" : "=l"(r) : "r"(u));
    return r;
}
__device__ __forceinline__ void ffma2(u64& a, u64 w, u64 x) {
    asm("fma.rn.f32x2 %0, %1, %2, %0;" : "+l"(a) : "l"(w), "l"(x));
}
__device__ __forceinline__ float2 upk(u64 a) {
    unsigned lo, hi;
    asm("mov.b64 {%0, %1}, %2;" : "=r"(lo), "=r"(hi) : "l"(a));
    return make_float2(__uint_as_float(lo), __uint_as_float(hi));
}

// ---------------- stage weights [M][K] -> smem k-major, padded ------------
template <int M, int K, int NT>
__device__ __forceinline__ void stage_w(float* Ws, const float* __restrict__ src,
                                        int tid) {
    constexpr int Mp = M + 1;
    if (K % 4 == 0) {
        for (int m = tid; m < M; m += NT) {
            const float4* row = (const float4*)(src + m * K);
#pragma unroll 4
            for (int k4 = 0; k4 < K / 4; k4++) {
                float4 v = row[k4];
                Ws[(4 * k4 + 0) * Mp + m] = v.x;
                Ws[(4 * k4 + 1) * Mp + m] = v.y;
                Ws[(4 * k4 + 2) * Mp + m] = v.z;
                Ws[(4 * k4 + 3) * Mp + m] = v.w;
            }
        }
    } else {
        for (int i = tid; i < M * K; i += NT) {
            int m = i / K, k = i - m * K;
            Ws[k * Mp + m] = src[i];
        }
    }
}

// ---------------- kNN: one warp per query point ---------------------------
__global__ __launch_bounds__(128)
void k_knn(const float* __restrict__ cloud, const float* __restrict__ cloud_tar) {
    __shared__ float sc[NPTS * 3];
    __shared__ float st[NPTS * 3];
    const int tid = threadIdx.x;
    for (int i = tid; i < NPTS * 3; i += 128) {
        sc[i] = cloud[i];
        st[i] = cloud_tar[i];
    }
    __syncthreads();

    const int warp = blockIdx.x * 4 + (tid >> 5);
    const int lane = tid & 31;
    if (warp >= 2 * NPTS) return;

    const bool tc = (warp >= NPTS);
    const int  q  = tc ? warp - NPTS : warp;
    const float* qs = tc ? st : sc;
    const float* rs = tc ? sc : st;

    const float qx = qs[q * 3 + 0], qy = qs[q * 3 + 1], qz = qs[q * 3 + 2];
    const float qq = qx * qx + qy * qy + qz * qz;
    const float INF = __int_as_float(0x7f800000);

    float vals[16];
#pragma unroll
    for (int k = 0; k < 16; k++) {
        int r = lane + 32 * k;
        if (r < NPTS) {
            float rx = rs[r * 3 + 0], ry = rs[r * 3 + 1], rz = rs[r * 3 + 2];
            float rr = rx * rx + ry * ry + rz * rz;
            float dt = qx * rx + qy * ry + qz * rz;
            vals[k] = fmaxf(qq - 2.f * dt + rr, 0.f);
        } else {
            vals[k] = INF;
        }
    }

    int*   oinds = tc ? g_inds_tc : g_inds;
    float* oexp  = tc ? g_expw_tc : g_expw;

    for (int r8 = 0; r8 < NNP; r8++) {
        float bv = vals[0];
        int   bk = 0;
#pragma unroll
        for (int k = 1; k < 16; k++)
            if (vals[k] < bv) { bv = vals[k]; bk = k; }
        u64 key = (((u64)__float_as_uint(bv)) << 32) | (unsigned)(lane + 32 * bk);
#pragma unroll
        for (int s = 16; s; s >>= 1) {
            u64 o = __shfl_xor_sync(0xffffffffu, key, s);
            if (o < key) key = o;
        }
        const int gi = (int)(key & 0xffffffffu);
#pragma unroll
        for (int k = 0; k < 16; k++)
            if (lane + 32 * k == gi) vals[k] = INF;
        if (lane == 0) {
            float dx = qx - rs[gi * 3 + 0];
            float dy = qy - rs[gi * 3 + 1];
            float dz = qz - rs[gi * 3 + 2];
            float nrm = sqrtf(dx * dx + dy * dy + dz * dz);
            oinds[q * NNP + r8] = gi;
            oexp [q * NNP + r8] = expf(-nrm);
        }
    }
}

// ---------------- fused 2-layer MLP, 256 threads, smem-staged weights -----
__host__ __device__ constexpr int ws_floats(int KIN, int KHID) {
    int a = KIN * (KHID + 1);
    int b = KHID * 129;
    return a > b ? a : b;
}
#define HPAD 36   // padded H row (floats); 144B = multiple of 16B
__host__ __device__ constexpr int mlp_smem_floats(int KIN, int KHID, int COLS) {
    return ws_floats(KIN, KHID) + KIN * COLS + KHID * HPAD + COLS + 256;
}

// Thread layout: trow = tid&127 (row), cgrp = tid>>7 (column half: 16 cols)
// GSEL: 0 = pconv (X = cloud [500][3], write g_cf)
//       1 = conv  (gather imf by g_inds, weighted mean -> g_sf)
//       2 = psconv(gather g_cf by g_inds_tc, weighted mean -> g_sfp)
template <int KIN, int KHID, int COLS, int GSEL>
__global__ __launch_bounds__(256, 1)
void k_mlp(const float* __restrict__ Xg,
           const float* __restrict__ w1, const float* __restrict__ b1,
           const float* __restrict__ w2, const float* __restrict__ b2) {
    constexpr int WS = ws_floats(KIN, KHID);
    constexpr int R1 = (KHID + 127) / 128;
    constexpr int JG = 8;                  // u64 per column group (16 cols)
    extern __shared__ float sm[];
    float* Ws  = sm;
    float* Xs  = sm + WS;
    float* Hs  = Xs + KIN * COLS;
    float* cw  = Hs + KHID * HPAD;
    float* red = cw + COLS;                // 256 partials

    const int tid  = threadIdx.x;
    const int trow = tid & 127;
    const int cgrp = tid >> 7;
    const int col0 = blockIdx.x * COLS;

    const int*   gidx = (GSEL == 1) ? g_inds : g_inds_tc;
    const float* ew   = (GSEL == 1) ? g_expw : g_expw_tc;

    if (GSEL != 0) {              // block-local deterministic softmax denom
        float s = 0.f;
        for (int i = tid; i < NSEL; i += 256) s += ew[i];
        red[tid] = s;
    }

    stage_w<KHID, KIN, 256>(Ws, w1, tid);

    const float* X = (GSEL == 2) ? (const float*)g_cf : Xg;
    for (int i = tid; i < KIN * COLS; i += 256) {
        int c = i % COLS, k = i / COLS;
        int col = col0 + c;
        float v = 0.f;
        if (GSEL == 0) {
            if (col < NPTS) v = X[col * 3 + k];        // cloud is [500][3]
        } else {
            v = X[k * NPTS + gidx[col]];
        }
        Xs[k * COLS + c] = v;
    }
    __syncthreads();

    if (GSEL != 0 && tid < 32) {
        float s = 0.f;
#pragma unroll
        for (int i = 0; i < 8; i++) s += red[tid + 32 * i];
#pragma unroll
        for (int o = 16; o; o >>= 1) s += __shfl_xor_sync(0xffffffffu, s, o);
        if (tid == 0) red[0] = 1.f / (8.f * s);
    }

    // ---- phase 1: H = lrelu(W1 @ X + b1); thread = (row-block, col half) --
    u64 acc[R1][JG];
#pragma unroll
    for (int rr = 0; rr < R1; rr++)
#pragma unroll
        for (int j = 0; j < JG; j++) acc[rr][j] = 0ull;

    for (int k = 0; k < KIN; k++) {
        const u64* xp = (const u64*)(Xs + k * COLS + cgrp * 16);
        u64 xv[JG];
#pragma unroll
        for (int j = 0; j < JG; j++) xv[j] = xp[j];
#pragma unroll
        for (int rr = 0; rr < R1; rr++) {
            int row = trow + rr * 128;
            if ((KHID % 128 == 0) || row < KHID) {
                u64 wp = packww(Ws[k * (KHID + 1) + row]);
#pragma unroll
                for (int j = 0; j < JG; j++) ffma2(acc[rr][j], wp, xv[j]);
            }
        }
    }
#pragma unroll
    for (int rr = 0; rr < R1; rr++) {
        int row = trow + rr * 128;
        if (row < KHID) {
            float b = b1[row];
#pragma unroll
            for (int j = 0; j < JG; j++) {
                float2 v = upk(acc[rr][j]);
                v.x += b; v.y += b;
                v.x = (v.x >= 0.f) ? v.x : 0.01f * v.x;
                v.y = (v.y >= 0.f) ? v.y : 0.01f * v.y;
                *(float2*)(Hs + row * HPAD + cgrp * 16 + 2 * j) = v;
            }
        }
    }
    __syncthreads();

    stage_w<128, KHID, 256>(Ws, w2, tid);  // overwrite Ws with W2 (post-sync)
    if (GSEL != 0 && tid < COLS)
        cw[tid] = ew[col0 + tid] * red[0];
    __syncthreads();

    // ---- phase 2: Y = W2 @ H + b2 ----
    u64 a2[JG];
#pragma unroll
    for (int j = 0; j < JG; j++) a2[j] = 0ull;
    for (int k = 0; k < KHID; k++) {
        const u64* hp = (const u64*)(Hs + k * HPAD + cgrp * 16);
        u64 xv[JG];
#pragma unroll
        for (int j = 0; j < JG; j++) xv[j] = hp[j];
        u64 wp = packww(Ws[k * 129 + trow]);
#pragma unroll
        for (int j = 0; j < JG; j++) ffma2(a2[j], wp, xv[j]);
    }
    float bb = b2[trow];

    if (GSEL == 0) {
#pragma unroll
        for (int j = 0; j < JG; j++) {
            float2 v = upk(a2[j]);
            int c = cgrp * 16 + 2 * j;
            if (col0 + c < NPTS)     g_cf[trow * NPTS + col0 + c]     = v.x + bb;
            if (col0 + c + 1 < NPTS) g_cf[trow * NPTS + col0 + c + 1] = v.y + bb;
        }
    } else {
        float* outb = (GSEL == 1) ? g_sf : g_sfp;
#pragma unroll
        for (int p = 0; p < 2; p++) {        // two 8-col groups per col half
            float s = 0.f;
#pragma unroll
            for (int j = 0; j < 4; j++) {
                float2 v = upk(a2[p * 4 + j]);
                int c = cgrp * 16 + p * 8 + 2 * j;
                s += (v.x + bb) * cw[c];
                s += (v.y + bb) * cw[c + 1];
            }
            outb[trow * NPTS + (col0 >> 3) + cgrp * 2 + p] = s;
        }
    }
}

// ---------------- final FC stack (256 threads) -----------------------------
// f1 = Wfc1 @ [sf; cf], f2 = Wfc2 @ [sfp; imf], out = Wfc @ lrelu([f2; f1])
#define FW2 10400   // 160*65
#define FW1 16640   // 256*65
#define FWF 8320    // 128*65
#define GP  20      // padded G row (floats); 80B = multiple of 16B
#define FINAL_SMEM_FLOATS (FW2 + FW1 + FWF + 256*16 + 160*16 + 128*GP)

__global__ __launch_bounds__(256, 1)
void k_final(const float* __restrict__ imf,
             const float* __restrict__ wf1, const float* __restrict__ bf1,
             const float* __restrict__ wf2, const float* __restrict__ bf2,
             const float* __restrict__ wf,  const float* __restrict__ bf,
             float* __restrict__ out) {
    extern __shared__ float sm[];
    float* W2s = sm;              // [160][65]
    float* W1s = W2s + FW2;       // [256][65]
    float* WFs = W1s + FW1;       // [128][65]
    float* X1  = WFs + FWF;       // [256][16]
    float* X2  = X1 + 256 * 16;   // [160][16]
    float* G   = X2 + 160 * 16;   // [128][GP]

    const int tid  = threadIdx.x;
    const int trow = tid & 127;
    const int cgrp = tid >> 7;    // 8-col half of the 16-col tile
    const int col0 = blockIdx.x * 16;

    stage_w<64, 160, 256>(W2s, wf2, tid);
    stage_w<64, 256, 256>(W1s, wf1, tid);
    stage_w<64, 128, 256>(WFs, wf,  tid);

    for (int i = tid; i < 256 * 16; i += 256) {
        int c = i & 15, k = i >> 4;
        int col = col0 + c;
        float v = 0.f;
        if (col < NPTS)
            v = (k < 128) ? g_sf[k * NPTS + col] : g_cf[(k - 128) * NPTS + col];
        X1[k * 16 + c] = v;
    }
    for (int i = tid; i < 160 * 16; i += 256) {
        int c = i & 15, k = i >> 4;
        int col = col0 + c;
        float v = 0.f;
        if (col < NPTS)
            v = (k < 128) ? g_sfp[k * NPTS + col] : imf[(k - 128) * NPTS + col];
        X2[k * 16 + c] = v;
    }
    __syncthreads();

    // Phase A: G = lrelu([f2; f1]); row = trow (f2: 0..63, f1: 64..127)
    u64 a[4];
#pragma unroll
    for (int j = 0; j < 4; j++) a[j] = 0ull;
    float b;
    if (trow < 64) {              // f2 rows (concat order [f2; f1])
        for (int k = 0; k < 160; k++) {
            const u64* xp = (const u64*)(X2 + k * 16 + cgrp * 8);
            u64 wp = packww(W2s[k * 65 + trow]);
#pragma unroll
            for (int j = 0; j < 4; j++) ffma2(a[j], wp, xp[j]);
        }
        b = bf2[trow];
    } else {                      // f1 rows
        for (int k = 0; k < 256; k++) {
            const u64* xp = (const u64*)(X1 + k * 16 + cgrp * 8);
            u64 wp = packww(W1s[k * 65 + (trow - 64)]);
#pragma unroll
            for (int j = 0; j < 4; j++) ffma2(a[j], wp, xp[j]);
        }
        b = bf1[trow - 64];
    }
#pragma unroll
    for (int j = 0; j < 4; j++) {
        float2 v = upk(a[j]);
        v.x += b; v.y += b;
        v.x = (v.x >= 0.f) ? v.x : 0.01f * v.x;
        v.y = (v.y >= 0.f) ? v.y : 0.01f * v.y;
        *(float2*)(G + trow * GP + cgrp * 8 + 2 * j) = v;
    }
    __syncthreads();

    // Phase B: out = Wfc @ G; 64 rows x 16 cols -> 4 groups of 4 cols
    {
        const int rowB = tid & 63;
        const int grpB = tid >> 6;     // 0..3, each 4 cols (2 u64)
        u64 o[2];
        o[0] = 0ull; o[1] = 0ull;
        for (int k = 0; k < 128; k++) {
            const u64* gp = (const u64*)(G + k * GP + grpB * 4);
            u64 wp = packww(WFs[k * 65 + rowB]);
            ffma2(o[0], wp, gp[0]);
            ffma2(o[1], wp, gp[1]);
        }
        float bb = bf[rowB];
#pragma unroll
        for (int j = 0; j < 2; j++) {
            float2 v = upk(o[j]);
            int c = grpB * 4 + 2 * j;
            if (col0 + c < NPTS)     out[rowB * NPTS + col0 + c]     = v.x + bb;
            if (col0 + c + 1 < NPTS) out[rowB * NPTS + col0 + c + 1] = v.y + bb;
        }
    }
}

// ---------------- launch ---------------------------------------------------
extern "C" void kernel_launch(void* const* d_in, const int* in_sizes, int n_in,
                              void* d_out, int out_size) {
    const float* imf       = (const float*)d_in[0];
    const float* cloud     = (const float*)d_in[1];
    const float* cloud_tar = (const float*)d_in[2];
    const float* w_conv1   = (const float*)d_in[3];
    const float* b_conv1   = (const float*)d_in[4];
    const float* w_conv2   = (const float*)d_in[5];
    const float* b_conv2   = (const float*)d_in[6];
    const float* w_psconv1 = (const float*)d_in[7];
    const float* b_psconv1 = (const float*)d_in[8];
    const float* w_psconv2 = (const float*)d_in[9];
    const float* b_psconv2 = (const float*)d_in[10];
    const float* w_pconv1  = (const float*)d_in[11];
    const float* b_pconv1  = (const float*)d_in[12];
    const float* w_pconv2  = (const float*)d_in[13];
    const float* b_pconv2  = (const float*)d_in[14];
    const float* w_fc1     = (const float*)d_in[15];
    const float* b_fc1     = (const float*)d_in[16];
    const float* w_fc2     = (const float*)d_in[17];
    const float* b_fc2     = (const float*)d_in[18];
    const float* w_fc      = (const float*)d_in[19];
    const float* b_fc      = (const float*)d_in[20];
    float* out = (float*)d_out;

    const int S0 = mlp_smem_floats(3, 64, 32) * 4;
    const int S1 = mlp_smem_floats(32, 64, 32) * 4;
    const int S2 = mlp_smem_floats(128, 256, 32) * 4;
    const int SF = FINAL_SMEM_FLOATS * 4;

    cudaFuncSetAttribute(k_mlp<3, 64, 32, 0>,
                         cudaFuncAttributeMaxDynamicSharedMemorySize, S0);
    cudaFuncSetAttribute(k_mlp<32, 64, 32, 1>,
                         cudaFuncAttributeMaxDynamicSharedMemorySize, S1);
    cudaFuncSetAttribute(k_mlp<128, 256, 32, 2>,
                         cudaFuncAttributeMaxDynamicSharedMemorySize, S2);
    cudaFuncSetAttribute(k_final,
                         cudaFuncAttributeMaxDynamicSharedMemorySize, SF);

    k_knn<<<250, 128>>>(cloud, cloud_tar);

    // cloud_feat: 3 -> 64 -> 128 over 500 points
    k_mlp<3, 64, 32, 0><<<(NPTS + 31) / 32, 256, S0>>>(
        cloud, w_pconv1, b_pconv1, w_pconv2, b_pconv2);

    // sf: gather imf by inds, 32 -> 64 -> 128, softmax-weighted mean8
    k_mlp<32, 64, 32, 1><<<NSEL / 32, 256, S1>>>(
        imf, w_conv1, b_conv1, w_conv2, b_conv2);

    // sfp: gather cloud_feat by inds_tc, 128 -> 256 -> 128, weighted mean8
    k_mlp<128, 256, 32, 2><<<NSEL / 32, 256, S2>>>(
        nullptr, w_psconv1, b_psconv1, w_psconv2, b_psconv2);

    k_final<<<(NPTS + 15) / 16, 256, SF>>>(
        imf, w_fc1, b_fc1, w_fc2, b_fc2, w_fc, b_fc, out);
}